// round 9
// baseline (speedup 1.0000x reference)
#include <cuda_runtime.h>
#include <cstdint>

// ImageWarpingLayer: out = bilinear_sample(image, grid + flow)
// image: [B=16, H=512, W=512, C=8] f32   flow: [B, H, W, 2] f32 (dy, dx)
// TF dense_image_warp semantics: floor clamped to [0, size-2],
// alpha = clip(q - floor, 0, 1).
//
// Persistent blocks (148 SMs x 8 CTAs), each looping over tiles of 512
// work-units (unit = pixel x float4-half-of-C, 2 threads/pixel, LDG.128
// gathers). Output staged in a double-buffered SMEM ring; each 8KB tile is
// written with one cp.async.bulk (TMA) that drains while the next tile is
// computed. Only a wait_group.read 1 throttle per iteration.

#define Bn 16
#define Hn 512
#define Wn 512
#define Cn 8

#define UNITS_PER_TILE 512              // 2 units per thread, 256 threads
#define TOTAL_UNITS (Bn * Hn * Wn * 2)  // 8388608
#define NUM_TILES (TOTAL_UNITS / UNITS_PER_TILE)  // 16384

#define GRID_BLOCKS (148 * 8)           // 1184 persistent CTAs

#define ROW_BYTES (Wn * Cn * 4)         // 16384 bytes per image row
#define PIX_BYTES (Cn * 4)              // 32 bytes per pixel

__device__ __forceinline__ uint32_t smem_u32(const void* p) {
    uint32_t a;
    asm("{ .reg .u64 t; cvta.to.shared.u64 t, %1; cvt.u32.u64 %0, t; }"
        : "=r"(a) : "l"(p));
    return a;
}

__global__ __launch_bounds__(256, 8)
void warp_kernel(const char* __restrict__ image,
                 const float* __restrict__ flow,
                 float* __restrict__ out)
{
    __shared__ __align__(16) float4 buf[2][UNITS_PER_TILE];  // 2 x 8 KB

    const int t = threadIdx.x;
    int stage = 0;

    for (int tile = blockIdx.x; tile < NUM_TILES; tile += GRID_BLOCKS) {
        const int base = tile * UNITS_PER_TILE;

        // Ensure the TMA issued 2 iterations ago (same stage) has finished
        // reading this smem buffer. At most 1 group may remain in flight.
        if (t == 0) {
            asm volatile("cp.async.bulk.wait_group.read 1;" ::: "memory");
        }
        __syncthreads();

#pragma unroll
        for (int k = 0; k < 2; k++) {
            const int slot = t + k * 256;
            const int uid  = base + slot;

            const int pix  = uid >> 1;      // pixel id ((b*H + y)*W + x)
            const int half = uid & 1;       // which float4 half of C

            const int x = pix & (Wn - 1);
            const int y = (pix >> 9) & (Hn - 1);
            const int b = pix >> 18;

            const float2 f = __ldg(reinterpret_cast<const float2*>(flow) + pix);
            const float qy = (float)y + f.x;
            const float qx = (float)x + f.y;

            const float fy = fminf(fmaxf(floorf(qy), 0.0f), (float)(Hn - 2));
            const float fx = fminf(fmaxf(floorf(qx), 0.0f), (float)(Wn - 2));
            const float ay = fminf(fmaxf(qy - fy, 0.0f), 1.0f);
            const float ax = fminf(fmaxf(qx - fx, 0.0f), 1.0f);

            const int iy = (int)fy;
            const int ix = (int)fx;

            // 32-bit byte offsets (image spans 2^27 bytes)
            const uint32_t top = (uint32_t)(b * Hn + iy) * ROW_BYTES
                               + (uint32_t)ix * PIX_BYTES + (uint32_t)(half << 4);
            const uint32_t bot = top + ROW_BYTES;

            const float4 tl = __ldg(reinterpret_cast<const float4*>(image + top));
            const float4 tr = __ldg(reinterpret_cast<const float4*>(image + top + PIX_BYTES));
            const float4 bl = __ldg(reinterpret_cast<const float4*>(image + bot));
            const float4 br = __ldg(reinterpret_cast<const float4*>(image + bot + PIX_BYTES));

            float4 o;
            float tt, bo;
            tt  = fmaf(ax, tr.x - tl.x, tl.x);
            bo  = fmaf(ax, br.x - bl.x, bl.x);
            o.x = fmaf(ay, bo - tt, tt);
            tt  = fmaf(ax, tr.y - tl.y, tl.y);
            bo  = fmaf(ax, br.y - bl.y, bl.y);
            o.y = fmaf(ay, bo - tt, tt);
            tt  = fmaf(ax, tr.z - tl.z, tl.z);
            bo  = fmaf(ax, br.z - bl.z, bl.z);
            o.z = fmaf(ay, bo - tt, tt);
            tt  = fmaf(ax, tr.w - tl.w, tl.w);
            bo  = fmaf(ax, br.w - bl.w, bl.w);
            o.w = fmaf(ay, bo - tt, tt);

            buf[stage][slot] = o;  // STS.128, conflict-free
        }

        __syncthreads();

        if (t == 0) {
            asm volatile("fence.proxy.async.shared::cta;" ::: "memory");
            const uint32_t s = smem_u32(buf[stage]);
            float* g = out + (long)base * 4;  // 4 floats per unit
            asm volatile(
                "cp.async.bulk.global.shared::cta.bulk_group [%0], [%1], %2;"
                :: "l"(g), "r"(s), "n"(UNITS_PER_TILE * 16) : "memory");
            asm volatile("cp.async.bulk.commit_group;" ::: "memory");
        }

        stage ^= 1;
    }

    // Drain all outstanding TMA stores before exit.
    if (t == 0) {
        asm volatile("cp.async.bulk.wait_group.read 0;" ::: "memory");
    }
}

extern "C" void kernel_launch(void* const* d_in, const int* in_sizes, int n_in,
                              void* d_out, int out_size)
{
    const char*  image = (const char*)d_in[0];
    const float* flow  = (const float*)d_in[1];
    float* out = (float*)d_out;

    warp_kernel<<<GRID_BLOCKS, 256>>>(image, flow, out);
}

// round 10
// speedup vs baseline: 1.0371x; 1.0371x over previous
#include <cuda_runtime.h>
#include <cstdint>

// ImageWarpingLayer: out = bilinear_sample(image, grid + flow)
// image: [B=16, H=512, W=512, C=8] f32   flow: [B, H, W, 2] f32 (dy, dx)
// TF dense_image_warp semantics: floor clamped to [0, size-2],
// alpha = clip(q - floor, 0, 1).
//
// 4 lanes per pixel. Lane quarter q loads top-row bytes [q*16, q*16+16) and
// bottom-row bytes [((q+2)&3)*16, ...+16): ONE LDG.128 instruction covers the
// full 64B top row of 8 pixels (no duplicate line touches; ~3 lines/instr),
// one more covers the bottom row. Each lane combines its two corners with
// bilinear product weights; a single shfl_xor(2) exchange + add produces the
// final 4 output channels on lanes q<2. Output staged in SMEM, stored with
// split cp.async.bulk (TMA) overlapped with compute of the second half.

#define Bn 16
#define Hn 512
#define Wn 512
#define Cn 8

#define PIX_PER_BLOCK 256               // 256 threads, 4 lanes/px, 4 iters
#define TOTAL_PIX (Bn * Hn * Wn)        // 4194304

#define ROW_BYTES (Wn * Cn * 4)         // 16384 bytes per image row
#define PIX_BYTES (Cn * 4)              // 32 bytes per pixel

__device__ __forceinline__ uint32_t smem_u32(const void* p) {
    uint32_t a;
    asm("{ .reg .u64 t; cvta.to.shared.u64 t, %1; cvt.u32.u64 %0, t; }"
        : "=r"(a) : "l"(p));
    return a;
}

__global__ __launch_bounds__(256, 8)
void warp_kernel(const char* __restrict__ image,
                 const float* __restrict__ flow,
                 float* __restrict__ out)
{
    __shared__ __align__(16) float4 buf[PIX_PER_BLOCK * 2];  // 8 KB

    const int t       = threadIdx.x;
    const int q       = t & 3;            // quarter within pixel
    const int base_px = blockIdx.x * PIX_PER_BLOCK;

#pragma unroll
    for (int k = 0; k < 4; k++) {
        const int px_local = (t >> 2) + k * 64;   // iter k covers px [k*64, k*64+64)
        const int pix      = base_px + px_local;

        const int x = pix & (Wn - 1);
        const int y = (pix >> 9) & (Hn - 1);
        const int b = pix >> 18;

        // 4 lanes of a pixel read the same float2 (dup sectors coalesce)
        const float2 f = __ldg(reinterpret_cast<const float2*>(flow) + pix);
        const float qy = (float)y + f.x;
        const float qx = (float)x + f.y;

        const float fy = fminf(fmaxf(floorf(qy), 0.0f), (float)(Hn - 2));
        const float fx = fminf(fmaxf(floorf(qx), 0.0f), (float)(Wn - 2));
        const float ay = fminf(fmaxf(qy - fy, 0.0f), 1.0f);
        const float ax = fminf(fmaxf(qx - fx, 0.0f), 1.0f);

        const int iy = (int)fy;
        const int ix = (int)fx;

        const uint32_t rowtop = (uint32_t)(b * Hn + iy) * ROW_BYTES
                              + (uint32_t)ix * PIX_BYTES;

        // top: quarters 0..3 cover [base, base+64) => lanes q<2 hold tl, q>=2 hold tr
        // bot: quarters rotated by 2 => lanes q<2 hold br, q>=2 hold bl
        const uint32_t top = rowtop + ((uint32_t)q << 4);
        const uint32_t bot = rowtop + ROW_BYTES + ((uint32_t)((q + 2) & 3) << 4);

        const float4 tv = __ldg(reinterpret_cast<const float4*>(image + top));
        const float4 bv = __ldg(reinterpret_cast<const float4*>(image + bot));

        // Bilinear product weights:
        //   q<2 : P = (1-ax)(1-ay)*tl + ax*ay*br
        //   q>=2: P = ax(1-ay)*tr + (1-ax)*ay*bl
        const bool lo = (q < 2);
        const float wt = lo ? (1.0f - ax) * (1.0f - ay) : ax * (1.0f - ay);
        const float wb = lo ? ax * ay                   : (1.0f - ax) * ay;

        float4 P;
        P.x = fmaf(tv.x, wt, bv.x * wb);
        P.y = fmaf(tv.y, wt, bv.y * wb);
        P.z = fmaf(tv.z, wt, bv.z * wb);
        P.w = fmaf(tv.w, wt, bv.w * wb);

        // Exchange partner's partial (lane^2 pairs q0<->q2, q1<->q3, same pixel)
        float4 o;
        o.x = P.x + __shfl_xor_sync(0xffffffffu, P.x, 2);
        o.y = P.y + __shfl_xor_sync(0xffffffffu, P.y, 2);
        o.z = P.z + __shfl_xor_sync(0xffffffffu, P.z, 2);
        o.w = P.w + __shfl_xor_sync(0xffffffffu, P.w, 2);

        // lanes q<2 hold the final channels [4q, 4q+4) for this pixel
        if (lo) {
            buf[px_local * 2 + q] = o;   // STS.128, contiguous per half-warp
        }

        // After the first two iters (px [0,128) staged = 4KB), kick TMA #1;
        // it drains while iters 2,3 compute. After iter 3, kick TMA #2.
        if (k == 1 || k == 3) {
            __syncthreads();
            if (t == 0) {
                asm volatile("fence.proxy.async.shared::cta;" ::: "memory");
                const int half = (k == 3);
                const uint32_t s = smem_u32(buf) + half * 4096;
                float* g = out + ((long)base_px + half * 128) * Cn;
                asm volatile(
                    "cp.async.bulk.global.shared::cta.bulk_group [%0], [%1], %2;"
                    :: "l"(g), "r"(s), "n"(4096) : "memory");
                asm volatile("cp.async.bulk.commit_group;" ::: "memory");
            }
        }
    }

    // t==0 issued the TMAs; ensure SMEM fully read before block exit.
    if (t == 0) {
        asm volatile("cp.async.bulk.wait_group.read 0;" ::: "memory");
    }
}

extern "C" void kernel_launch(void* const* d_in, const int* in_sizes, int n_in,
                              void* d_out, int out_size)
{
    const char*  image = (const char*)d_in[0];
    const float* flow  = (const float*)d_in[1];
    float* out = (float*)d_out;

    const int blocks = TOTAL_PIX / PIX_PER_BLOCK; // 16384
    warp_kernel<<<blocks, 256>>>(image, flow, out);
}

// round 11
// speedup vs baseline: 1.0488x; 1.0113x over previous
#include <cuda_runtime.h>
#include <cstdint>

// ImageWarpingLayer: out = bilinear_sample(image, grid + flow)
// image: [B=16, H=512, W=512, C=8] f32   flow: [B, H, W, 2] f32 (dy, dx)
// TF dense_image_warp semantics: floor clamped to [0, size-2],
// alpha = clip(q - floor, 0, 1).
//
// Work-unit = (pixel, float4-half-of-C): 2 threads/pixel, LDG.128 gathers.
// Warp-autonomous stores: each warp owns 64 contiguous output units (1KB),
// stages them in its private SMEM chunk, and issues its own cp.async.bulk
// (TMA) with no block-level barriers at all - removes inter-warp skew
// serialization that the __syncthreads-based variants pay.

#define Bn 16
#define Hn 512
#define Wn 512
#define Cn 8

#define UNITS_PER_BLOCK 512             // 8 warps x 64 units
#define TOTAL_UNITS (Bn * Hn * Wn * 2)  // 8388608

#define ROW_BYTES (Wn * Cn * 4)         // 16384 bytes per image row
#define PIX_BYTES (Cn * 4)              // 32 bytes per pixel

__device__ __forceinline__ uint32_t smem_u32(const void* p) {
    uint32_t a;
    asm("{ .reg .u64 t; cvta.to.shared.u64 t, %1; cvt.u32.u64 %0, t; }"
        : "=r"(a) : "l"(p));
    return a;
}

__global__ __launch_bounds__(256, 8)
void warp_kernel(const char* __restrict__ image,
                 const float* __restrict__ flow,
                 float* __restrict__ out)
{
    __shared__ __align__(16) float4 buf[UNITS_PER_BLOCK];  // 8 KB

    const int t    = threadIdx.x;
    const int w    = t >> 5;            // warp id (0..7)
    const int lane = t & 31;

    const int base  = blockIdx.x * UNITS_PER_BLOCK;
    const int wbase = base + w * 64;    // this warp's 64 contiguous units

#pragma unroll
    for (int k = 0; k < 2; k++) {
        const int uid  = wbase + k * 32 + lane;
        const int slot = w * 64 + k * 32 + lane;   // warp-private smem chunk

        const int pix  = uid >> 1;      // pixel id ((b*H + y)*W + x)
        const int half = uid & 1;       // which float4 half of C

        const int x = pix & (Wn - 1);
        const int y = (pix >> 9) & (Hn - 1);
        const int b = pix >> 18;

        const float2 f = __ldg(reinterpret_cast<const float2*>(flow) + pix);
        const float qy = (float)y + f.x;
        const float qx = (float)x + f.y;

        const float fy = fminf(fmaxf(floorf(qy), 0.0f), (float)(Hn - 2));
        const float fx = fminf(fmaxf(floorf(qx), 0.0f), (float)(Wn - 2));
        const float ay = fminf(fmaxf(qy - fy, 0.0f), 1.0f);
        const float ax = fminf(fmaxf(qx - fx, 0.0f), 1.0f);

        const int iy = (int)fy;
        const int ix = (int)fx;

        // 32-bit byte offsets (image spans 2^27 bytes)
        const uint32_t top = (uint32_t)(b * Hn + iy) * ROW_BYTES
                           + (uint32_t)ix * PIX_BYTES + (uint32_t)(half << 4);
        const uint32_t bot = top + ROW_BYTES;

        const float4 tl = __ldg(reinterpret_cast<const float4*>(image + top));
        const float4 tr = __ldg(reinterpret_cast<const float4*>(image + top + PIX_BYTES));
        const float4 bl = __ldg(reinterpret_cast<const float4*>(image + bot));
        const float4 br = __ldg(reinterpret_cast<const float4*>(image + bot + PIX_BYTES));

        float4 o;
        float tt, bo;
        tt  = fmaf(ax, tr.x - tl.x, tl.x);
        bo  = fmaf(ax, br.x - bl.x, bl.x);
        o.x = fmaf(ay, bo - tt, tt);
        tt  = fmaf(ax, tr.y - tl.y, tl.y);
        bo  = fmaf(ax, br.y - bl.y, bl.y);
        o.y = fmaf(ay, bo - tt, tt);
        tt  = fmaf(ax, tr.z - tl.z, tl.z);
        bo  = fmaf(ax, br.z - bl.z, bl.z);
        o.z = fmaf(ay, bo - tt, tt);
        tt  = fmaf(ax, tr.w - tl.w, tl.w);
        bo  = fmaf(ax, br.w - bl.w, bl.w);
        o.w = fmaf(ay, bo - tt, tt);

        buf[slot] = o;  // STS.128 into warp-private chunk, conflict-free
    }

    // Warp-local publish: no block barrier. Lane 0 issues this warp's 1KB
    // TMA store and waits only for the smem read to complete before exit
    // (smem chunk may be reused by the next CTA on this SM slot).
    __syncwarp();
    if (lane == 0) {
        asm volatile("fence.proxy.async.shared::cta;" ::: "memory");
        const uint32_t s = smem_u32(buf) + (uint32_t)(w * 64 * 16);
        float* g = out + (long)wbase * 4;  // 4 floats per unit
        asm volatile(
            "cp.async.bulk.global.shared::cta.bulk_group [%0], [%1], %2;"
            :: "l"(g), "r"(s), "n"(64 * 16) : "memory");
        asm volatile("cp.async.bulk.commit_group;" ::: "memory");
        asm volatile("cp.async.bulk.wait_group.read 0;" ::: "memory");
    }
}

extern "C" void kernel_launch(void* const* d_in, const int* in_sizes, int n_in,
                              void* d_out, int out_size)
{
    const char*  image = (const char*)d_in[0];
    const float* flow  = (const float*)d_in[1];
    float* out = (float*)d_out;

    const int blocks = TOTAL_UNITS / UNITS_PER_BLOCK; // 16384
    warp_kernel<<<blocks, 256>>>(image, flow, out);
}

// round 12
// speedup vs baseline: 1.1315x; 1.0788x over previous
#include <cuda_runtime.h>
#include <cstdint>

// ImageWarpingLayer: out = bilinear_sample(image, grid + flow)
// image: [B=16, H=512, W=512, C=8] f32   flow: [B, H, W, 2] f32 (dy, dx)
// TF dense_image_warp semantics: floor clamped to [0, size-2],
// alpha = clip(q - floor, 0, 1).
//
// R8 config with 128-thread blocks: work-unit = (pixel, float4-half-of-C),
// 2 threads/pixel, LDG.128 gathers, 2 units/thread. Output staged in SMEM;
// each 2KB half is TMA-bulk-stored as soon as ready (first store overlaps
// second half's compute). Smaller blocks = max-of-4-warp barrier skew
// instead of max-of-8, and finer wave-tail balancing.

#define Bn 16
#define Hn 512
#define Wn 512
#define Cn 8

#define THREADS 128
#define UNITS_PER_BLOCK 256             // 2 units per thread
#define HALF_UNITS_BLK  128
#define TOTAL_UNITS (Bn * Hn * Wn * 2)  // 8388608

#define ROW_BYTES (Wn * Cn * 4)         // 16384 bytes per image row
#define PIX_BYTES (Cn * 4)              // 32 bytes per pixel

__device__ __forceinline__ uint32_t smem_u32(const void* p) {
    uint32_t a;
    asm("{ .reg .u64 t; cvta.to.shared.u64 t, %1; cvt.u32.u64 %0, t; }"
        : "=r"(a) : "l"(p));
    return a;
}

__global__ __launch_bounds__(THREADS, 16)
void warp_kernel(const char* __restrict__ image,
                 const float* __restrict__ flow,
                 float* __restrict__ out)
{
    __shared__ __align__(16) float4 buf[UNITS_PER_BLOCK];  // 4 KB

    const int base = blockIdx.x * UNITS_PER_BLOCK;
    const int t    = threadIdx.x;

    // ---- front-batched flow loads for both halves ----
    float2 f[2];
#pragma unroll
    for (int k = 0; k < 2; k++) {
        const int pix = (base + t + k * HALF_UNITS_BLK) >> 1;
        f[k] = __ldg(reinterpret_cast<const float2*>(flow) + pix);
    }

#pragma unroll
    for (int k = 0; k < 2; k++) {
        const int slot = t + k * HALF_UNITS_BLK;
        const int uid  = base + slot;

        const int pix  = uid >> 1;      // pixel id ((b*H + y)*W + x)
        const int half = uid & 1;       // which float4 half of C

        const int x = pix & (Wn - 1);
        const int y = (pix >> 9) & (Hn - 1);
        const int b = pix >> 18;

        const float qy = (float)y + f[k].x;
        const float qx = (float)x + f[k].y;

        const float fy = fminf(fmaxf(floorf(qy), 0.0f), (float)(Hn - 2));
        const float fx = fminf(fmaxf(floorf(qx), 0.0f), (float)(Wn - 2));
        const float ay = fminf(fmaxf(qy - fy, 0.0f), 1.0f);
        const float ax = fminf(fmaxf(qx - fx, 0.0f), 1.0f);

        const int iy = (int)fy;
        const int ix = (int)fx;

        // 32-bit byte offsets (image spans 2^27 bytes)
        const uint32_t top = (uint32_t)(b * Hn + iy) * ROW_BYTES
                           + (uint32_t)ix * PIX_BYTES + (uint32_t)(half << 4);
        const uint32_t bot = top + ROW_BYTES;

        const float4 tl = __ldg(reinterpret_cast<const float4*>(image + top));
        const float4 tr = __ldg(reinterpret_cast<const float4*>(image + top + PIX_BYTES));
        const float4 bl = __ldg(reinterpret_cast<const float4*>(image + bot));
        const float4 br = __ldg(reinterpret_cast<const float4*>(image + bot + PIX_BYTES));

        float4 o;
        float tt, bo;
        tt  = fmaf(ax, tr.x - tl.x, tl.x);
        bo  = fmaf(ax, br.x - bl.x, bl.x);
        o.x = fmaf(ay, bo - tt, tt);
        tt  = fmaf(ax, tr.y - tl.y, tl.y);
        bo  = fmaf(ax, br.y - bl.y, bl.y);
        o.y = fmaf(ay, bo - tt, tt);
        tt  = fmaf(ax, tr.z - tl.z, tl.z);
        bo  = fmaf(ax, br.z - bl.z, bl.z);
        o.z = fmaf(ay, bo - tt, tt);
        tt  = fmaf(ax, tr.w - tl.w, tl.w);
        bo  = fmaf(ax, br.w - bl.w, bl.w);
        o.w = fmaf(ay, bo - tt, tt);

        buf[slot] = o;  // STS.128, conflict-free

        // After half k is staged, kick its 2KB TMA store; the k=0 store
        // drains while the block computes k=1.
        __syncthreads();
        if (t == 0) {
            asm volatile("fence.proxy.async.shared::cta;" ::: "memory");
            const uint32_t s = smem_u32(buf) + k * (HALF_UNITS_BLK * 16);
            float* g = out + (long)(base + k * HALF_UNITS_BLK) * 4;
            asm volatile(
                "cp.async.bulk.global.shared::cta.bulk_group [%0], [%1], %2;"
                :: "l"(g), "r"(s), "n"(HALF_UNITS_BLK * 16) : "memory");
            asm volatile("cp.async.bulk.commit_group;" ::: "memory");
        }
    }

    // t==0 issued the TMAs; ensure SMEM fully read before block exit.
    if (t == 0) {
        asm volatile("cp.async.bulk.wait_group.read 0;" ::: "memory");
    }
}

extern "C" void kernel_launch(void* const* d_in, const int* in_sizes, int n_in,
                              void* d_out, int out_size)
{
    const char*  image = (const char*)d_in[0];
    const float* flow  = (const float*)d_in[1];
    float* out = (float*)d_out;

    const int blocks = TOTAL_UNITS / UNITS_PER_BLOCK; // 32768
    warp_kernel<<<blocks, THREADS>>>(image, flow, out);
}

// round 13
// speedup vs baseline: 1.1442x; 1.0113x over previous
#include <cuda_runtime.h>
#include <cstdint>

// ImageWarpingLayer: out = bilinear_sample(image, grid + flow)
// image: [B=16, H=512, W=512, C=8] f32   flow: [B, H, W, 2] f32 (dy, dx)
// TF dense_image_warp semantics: floor clamped to [0, size-2],
// alpha = clip(q - floor, 0, 1).
//
// R12 config (128-thread blocks, 2 units/thread, LDG.128 gathers, SMEM-
// staged split TMA bulk stores) + L1 cache-policy hints:
//   image gathers  -> ld.global.nc.L1::evict_last  (neighbor warps reuse lines)
//   flow loads     -> ld.global.nc.L1::evict_first (streaming, use-once)

#define Bn 16
#define Hn 512
#define Wn 512
#define Cn 8

#define THREADS 128
#define UNITS_PER_BLOCK 256             // 2 units per thread
#define HALF_UNITS_BLK  128
#define TOTAL_UNITS (Bn * Hn * Wn * 2)  // 8388608

#define ROW_BYTES (Wn * Cn * 4)         // 16384 bytes per image row
#define PIX_BYTES (Cn * 4)              // 32 bytes per pixel

__device__ __forceinline__ uint32_t smem_u32(const void* p) {
    uint32_t a;
    asm("{ .reg .u64 t; cvta.to.shared.u64 t, %1; cvt.u32.u64 %0, t; }"
        : "=r"(a) : "l"(p));
    return a;
}

__device__ __forceinline__ float4 ldg_el(const void* p) {
    float4 v;
    asm("ld.global.nc.L1::evict_last.v4.f32 {%0,%1,%2,%3}, [%4];"
        : "=f"(v.x), "=f"(v.y), "=f"(v.z), "=f"(v.w) : "l"(p));
    return v;
}

__device__ __forceinline__ float2 ldg_ef2(const void* p) {
    float2 v;
    asm("ld.global.nc.L1::evict_first.v2.f32 {%0,%1}, [%2];"
        : "=f"(v.x), "=f"(v.y) : "l"(p));
    return v;
}

__global__ __launch_bounds__(THREADS, 16)
void warp_kernel(const char* __restrict__ image,
                 const float* __restrict__ flow,
                 float* __restrict__ out)
{
    __shared__ __align__(16) float4 buf[UNITS_PER_BLOCK];  // 4 KB

    const int base = blockIdx.x * UNITS_PER_BLOCK;
    const int t    = threadIdx.x;

    // ---- front-batched flow loads for both halves (streaming hint) ----
    float2 f[2];
#pragma unroll
    for (int k = 0; k < 2; k++) {
        const int pix = (base + t + k * HALF_UNITS_BLK) >> 1;
        f[k] = ldg_ef2(reinterpret_cast<const float2*>(flow) + pix);
    }

#pragma unroll
    for (int k = 0; k < 2; k++) {
        const int slot = t + k * HALF_UNITS_BLK;
        const int uid  = base + slot;

        const int pix  = uid >> 1;      // pixel id ((b*H + y)*W + x)
        const int half = uid & 1;       // which float4 half of C

        const int x = pix & (Wn - 1);
        const int y = (pix >> 9) & (Hn - 1);
        const int b = pix >> 18;

        const float qy = (float)y + f[k].x;
        const float qx = (float)x + f[k].y;

        const float fy = fminf(fmaxf(floorf(qy), 0.0f), (float)(Hn - 2));
        const float fx = fminf(fmaxf(floorf(qx), 0.0f), (float)(Wn - 2));
        const float ay = fminf(fmaxf(qy - fy, 0.0f), 1.0f);
        const float ax = fminf(fmaxf(qx - fx, 0.0f), 1.0f);

        const int iy = (int)fy;
        const int ix = (int)fx;

        // 32-bit byte offsets (image spans 2^27 bytes)
        const uint32_t top = (uint32_t)(b * Hn + iy) * ROW_BYTES
                           + (uint32_t)ix * PIX_BYTES + (uint32_t)(half << 4);
        const uint32_t bot = top + ROW_BYTES;

        const float4 tl = ldg_el(image + top);
        const float4 tr = ldg_el(image + top + PIX_BYTES);
        const float4 bl = ldg_el(image + bot);
        const float4 br = ldg_el(image + bot + PIX_BYTES);

        float4 o;
        float tt, bo;
        tt  = fmaf(ax, tr.x - tl.x, tl.x);
        bo  = fmaf(ax, br.x - bl.x, bl.x);
        o.x = fmaf(ay, bo - tt, tt);
        tt  = fmaf(ax, tr.y - tl.y, tl.y);
        bo  = fmaf(ax, br.y - bl.y, bl.y);
        o.y = fmaf(ay, bo - tt, tt);
        tt  = fmaf(ax, tr.z - tl.z, tl.z);
        bo  = fmaf(ax, br.z - bl.z, bl.z);
        o.z = fmaf(ay, bo - tt, tt);
        tt  = fmaf(ax, tr.w - tl.w, tl.w);
        bo  = fmaf(ax, br.w - bl.w, bl.w);
        o.w = fmaf(ay, bo - tt, tt);

        buf[slot] = o;  // STS.128, conflict-free

        // After half k is staged, kick its 2KB TMA store; the k=0 store
        // drains while the block computes k=1.
        __syncthreads();
        if (t == 0) {
            asm volatile("fence.proxy.async.shared::cta;" ::: "memory");
            const uint32_t s = smem_u32(buf) + k * (HALF_UNITS_BLK * 16);
            float* g = out + (long)(base + k * HALF_UNITS_BLK) * 4;
            asm volatile(
                "cp.async.bulk.global.shared::cta.bulk_group [%0], [%1], %2;"
                :: "l"(g), "r"(s), "n"(HALF_UNITS_BLK * 16) : "memory");
            asm volatile("cp.async.bulk.commit_group;" ::: "memory");
        }
    }

    // t==0 issued the TMAs; ensure SMEM fully read before block exit.
    if (t == 0) {
        asm volatile("cp.async.bulk.wait_group.read 0;" ::: "memory");
    }
}

extern "C" void kernel_launch(void* const* d_in, const int* in_sizes, int n_in,
                              void* d_out, int out_size)
{
    const char*  image = (const char*)d_in[0];
    const float* flow  = (const float*)d_in[1];
    float* out = (float*)d_out;

    const int blocks = TOTAL_UNITS / UNITS_PER_BLOCK; // 32768
    warp_kernel<<<blocks, THREADS>>>(image, flow, out);
}